// round 1
// baseline (speedup 1.0000x reference)
#include <cuda_runtime.h>
#include <cuda_bf16.h>

// Problem: MaskedSelfAttention  B=2, S=2048, E=1024, H=16, D=64, causal.
// Inputs (metadata order): x[2,2048,1024] f32, mask (ignored; exactly causal tril),
// Wq,Wk,Wv,Wo [1024,1024] f32, bo[1024] f32. Output [2,2048,1024] f32.

#define TS   2048
#define EMB  1024
#define NHEADS 16
#define HD   64
#define ROWS (2*TS)            // 4096 total rows (B*S)

// Scratch (allocation-free rule: __device__ globals)
__device__ float g_Q[ROWS*EMB];
__device__ float g_K[ROWS*EMB];
__device__ float g_V[ROWS*EMB];
__device__ float g_A[ROWS*EMB];

// ---------------------------------------------------------------------------
// GEMM: C[M,N] = A[M,K] * B[N,K]^T (+ bias[n])
// Block tile 128x64, BK=16, 256 threads, 8x4 micro-tile.
// ---------------------------------------------------------------------------
__global__ __launch_bounds__(256) void gemm_abt(
    const float* __restrict__ A, const float* __restrict__ B,
    const float* __restrict__ bias, float* __restrict__ C,
    int M, int N, int K)
{
    __shared__ float As[16][132];   // k-major, padded
    __shared__ float Bs[16][68];

    const int tid = threadIdx.x;
    const int tn  = tid & 15;       // col group (x4) -> 64 cols
    const int tm  = tid >> 4;       // row group (x8) -> 128 rows
    const int bm  = blockIdx.y * 128;
    const int bn  = blockIdx.x * 64;

    float acc[8][4];
#pragma unroll
    for (int i = 0; i < 8; i++)
#pragma unroll
        for (int j = 0; j < 4; j++) acc[i][j] = 0.f;

    for (int k0 = 0; k0 < K; k0 += 16) {
        // A tile: 128x16 -> As[k][m]
#pragma unroll
        for (int it = 0; it < 2; it++) {
            int v   = tid + it * 256;
            int row = v >> 2;
            int kq  = (v & 3) * 4;
            float4 t = *(const float4*)&A[(size_t)(bm + row) * K + k0 + kq];
            As[kq + 0][row] = t.x; As[kq + 1][row] = t.y;
            As[kq + 2][row] = t.z; As[kq + 3][row] = t.w;
        }
        // B tile: 64x16 -> Bs[k][n]
        {
            int row = tid >> 2;
            int kq  = (tid & 3) * 4;
            float4 t = *(const float4*)&B[(size_t)(bn + row) * K + k0 + kq];
            Bs[kq + 0][row] = t.x; Bs[kq + 1][row] = t.y;
            Bs[kq + 2][row] = t.z; Bs[kq + 3][row] = t.w;
        }
        __syncthreads();

#pragma unroll
        for (int k = 0; k < 16; k++) {
            float4 a0 = *(const float4*)&As[k][tm * 8];
            float4 a1 = *(const float4*)&As[k][tm * 8 + 4];
            float4 bb = *(const float4*)&Bs[k][tn * 4];
            float a[8] = {a0.x, a0.y, a0.z, a0.w, a1.x, a1.y, a1.z, a1.w};
            float b[4] = {bb.x, bb.y, bb.z, bb.w};
#pragma unroll
            for (int i = 0; i < 8; i++)
#pragma unroll
                for (int j = 0; j < 4; j++) acc[i][j] += a[i] * b[j];
        }
        __syncthreads();
    }

    float4 bv = make_float4(0.f, 0.f, 0.f, 0.f);
    if (bias) bv = *(const float4*)&bias[bn + tn * 4];
#pragma unroll
    for (int i = 0; i < 8; i++) {
        float4 r = make_float4(acc[i][0] + bv.x, acc[i][1] + bv.y,
                               acc[i][2] + bv.z, acc[i][3] + bv.w);
        *(float4*)&C[(size_t)(bm + tm * 8 + i) * N + bn + tn * 4] = r;
    }
}

// ---------------------------------------------------------------------------
// Flash attention (causal), fp32. One block = one (b,h) x 64-query tile.
// 256 threads; 4x4 micro-tiles for both score GEMM and PV GEMM.
// Qs/Ks stored d-major; P aliases the K buffer. 48 KB static smem.
// ---------------------------------------------------------------------------
__global__ __launch_bounds__(256) void attn_kernel(
    const float* __restrict__ Q, const float* __restrict__ K,
    const float* __restrict__ V, float* __restrict__ O)
{
    __shared__ float Qs[64 * 64];   // [d][q]
    __shared__ float KPs[64 * 64];  // [d][key], then reused as P[q][key]
    __shared__ float Vs[64 * 64];   // [key][d]

    const int tid   = threadIdx.x;
    const int tn    = tid & 15;     // key/d group (x4)
    const int tm    = tid >> 4;     // query group (x4)
    const int qtile = blockIdx.x;   // 0..31
    const int bh    = blockIdx.y;   // 0..63
    const int b     = bh >> 4;
    const int h     = bh & 15;
    const size_t base = (size_t)b * TS * EMB + (size_t)h * HD;

    // Load Q tile transposed: Qs[d][q]
#pragma unroll
    for (int it = 0; it < 4; it++) {
        int v   = tid + it * 256;
        int row = v >> 4;           // q 0..63
        int dq  = (v & 15) * 4;     // d
        float4 t = *(const float4*)&Q[base + (size_t)(qtile * 64 + row) * EMB + dq];
        Qs[(dq + 0) * 64 + row] = t.x; Qs[(dq + 1) * 64 + row] = t.y;
        Qs[(dq + 2) * 64 + row] = t.z; Qs[(dq + 3) * 64 + row] = t.w;
    }

    float m[4], l[4], o[4][4];
#pragma unroll
    for (int qi = 0; qi < 4; qi++) {
        m[qi] = -1e30f; l[qi] = 0.f;
#pragma unroll
        for (int di = 0; di < 4; di++) o[qi][di] = 0.f;
    }

    for (int kt = 0; kt <= qtile; kt++) {
        __syncthreads();   // previous iter's KPs/Vs reads done; Qs ready (1st iter)
        // Load K tile transposed into KPs[d][key], V into Vs[key][d]
#pragma unroll
        for (int it = 0; it < 4; it++) {
            int v   = tid + it * 256;
            int row = v >> 4;        // key 0..63
            int dq  = (v & 15) * 4;
            size_t g = base + (size_t)(kt * 64 + row) * EMB + dq;
            float4 tk = *(const float4*)&K[g];
            KPs[(dq + 0) * 64 + row] = tk.x; KPs[(dq + 1) * 64 + row] = tk.y;
            KPs[(dq + 2) * 64 + row] = tk.z; KPs[(dq + 3) * 64 + row] = tk.w;
            float4 tv = *(const float4*)&V[g];
            *(float4*)&Vs[row * 64 + dq] = tv;
        }
        __syncthreads();

        // Scores: s[qi][ki] = sum_d Qs[d][q] * KPs[d][k]
        float s[4][4];
#pragma unroll
        for (int qi = 0; qi < 4; qi++)
#pragma unroll
            for (int ki = 0; ki < 4; ki++) s[qi][ki] = 0.f;
#pragma unroll
        for (int d = 0; d < 64; d++) {
            float4 qf = *(const float4*)&Qs[d * 64 + tm * 4];
            float4 kf = *(const float4*)&KPs[d * 64 + tn * 4];
            float qa[4] = {qf.x, qf.y, qf.z, qf.w};
            float ka[4] = {kf.x, kf.y, kf.z, kf.w};
#pragma unroll
            for (int qi = 0; qi < 4; qi++)
#pragma unroll
                for (int ki = 0; ki < 4; ki++) s[qi][ki] += qa[qi] * ka[ki];
        }

        const float sc = 0.125f;  // 1/sqrt(64)
        if (kt == qtile) {
#pragma unroll
            for (int qi = 0; qi < 4; qi++) {
                int qg = qtile * 64 + tm * 4 + qi;
#pragma unroll
                for (int ki = 0; ki < 4; ki++) {
                    int kg = kt * 64 + tn * 4 + ki;
                    s[qi][ki] = (kg > qg) ? -1e30f : s[qi][ki] * sc;
                }
            }
        } else {
#pragma unroll
            for (int qi = 0; qi < 4; qi++)
#pragma unroll
                for (int ki = 0; ki < 4; ki++) s[qi][ki] *= sc;
        }

        __syncthreads();  // all score reads of KPs done; safe to overwrite with P

        // Online softmax per row; write P into KPs[q][key]
#pragma unroll
        for (int qi = 0; qi < 4; qi++) {
            float mt = fmaxf(fmaxf(s[qi][0], s[qi][1]), fmaxf(s[qi][2], s[qi][3]));
#pragma unroll
            for (int off = 1; off < 16; off <<= 1)
                mt = fmaxf(mt, __shfl_xor_sync(0xffffffffu, mt, off));
            float mn = fmaxf(m[qi], mt);
            float al = __expf(m[qi] - mn);
            float p[4], ps = 0.f;
#pragma unroll
            for (int ki = 0; ki < 4; ki++) { p[ki] = __expf(s[qi][ki] - mn); ps += p[ki]; }
#pragma unroll
            for (int off = 1; off < 16; off <<= 1)
                ps += __shfl_xor_sync(0xffffffffu, ps, off);
            l[qi] = l[qi] * al + ps;
            m[qi] = mn;
#pragma unroll
            for (int di = 0; di < 4; di++) o[qi][di] *= al;
            *(float4*)&KPs[(tm * 4 + qi) * 64 + tn * 4] = make_float4(p[0], p[1], p[2], p[3]);
        }
        __syncthreads();

        // PV: o[qi][di] += sum_k P[q][k] * Vs[k][d]
#pragma unroll
        for (int kk = 0; kk < 64; kk++) {
            float4 vf = *(const float4*)&Vs[kk * 64 + tn * 4];
            float va[4] = {vf.x, vf.y, vf.z, vf.w};
            float pq[4];
#pragma unroll
            for (int qi = 0; qi < 4; qi++) pq[qi] = KPs[(tm * 4 + qi) * 64 + kk];
#pragma unroll
            for (int qi = 0; qi < 4; qi++)
#pragma unroll
                for (int di = 0; di < 4; di++) o[qi][di] += pq[qi] * va[di];
        }
    }

    // Normalize and write: O[b, q, h, d]  (row b*S+q, col h*64+d)
#pragma unroll
    for (int qi = 0; qi < 4; qi++) {
        float inv = 1.f / l[qi];
        float4 r = make_float4(o[qi][0] * inv, o[qi][1] * inv,
                               o[qi][2] * inv, o[qi][3] * inv);
        *(float4*)&O[base + (size_t)(qtile * 64 + tm * 4 + qi) * EMB + tn * 4] = r;
    }
}

// ---------------------------------------------------------------------------
extern "C" void kernel_launch(void* const* d_in, const int* in_sizes, int n_in,
                              void* d_out, int out_size)
{
    const float* x  = (const float*)d_in[0];
    // d_in[1] = mask (causal tril) -- applied analytically, not read
    const float* Wq = (const float*)d_in[2];
    const float* Wk = (const float*)d_in[3];
    const float* Wv = (const float*)d_in[4];
    const float* Wo = (const float*)d_in[5];
    const float* bo = (const float*)d_in[6];
    float* out = (float*)d_out;

    float *Qb, *Kb, *Vb, *Ab;
    cudaGetSymbolAddress((void**)&Qb, g_Q);
    cudaGetSymbolAddress((void**)&Kb, g_K);
    cudaGetSymbolAddress((void**)&Vb, g_V);
    cudaGetSymbolAddress((void**)&Ab, g_A);

    dim3 ggrid(EMB / 64, ROWS / 128);   // (16, 32)
    gemm_abt<<<ggrid, 256>>>(x, Wq, nullptr, Qb, ROWS, EMB, EMB);
    gemm_abt<<<ggrid, 256>>>(x, Wk, nullptr, Kb, ROWS, EMB, EMB);
    gemm_abt<<<ggrid, 256>>>(x, Wv, nullptr, Vb, ROWS, EMB, EMB);

    dim3 agrid(TS / 64, 2 * NHEADS);    // (32, 64)
    attn_kernel<<<agrid, 256>>>(Qb, Kb, Vb, Ab);

    gemm_abt<<<ggrid, 256>>>(Ab, Wo, bo, out, ROWS, EMB, EMB);
}

// round 3
// speedup vs baseline: 1.5924x; 1.5924x over previous
#include <cuda_runtime.h>
#include <cuda_bf16.h>
#include <cstdint>

// Problem: MaskedSelfAttention  B=2, S=2048, E=1024, H=16, D=64, causal.
// R3: GEMMs via mma.sync.m16n8k8.tf32 (sm_103-safe legacy tensor path).
//     tcgen05 is NOT available: harness compiles PTX at target sm_103 (no 'a').

#define TS   2048
#define EMB  1024
#define NHEADS 16
#define HD   64
#define ROWS (2*TS)            // 4096 total rows (B*S)

__device__ float g_Q[ROWS*EMB];
__device__ float g_K[ROWS*EMB];
__device__ float g_V[ROWS*EMB];
__device__ float g_A[ROWS*EMB];

__device__ __forceinline__ uint32_t f2tf32(float f) {
    uint32_t u;
    asm("cvt.rna.tf32.f32 %0, %1;" : "=r"(u) : "f"(f));
    return u;
}

__device__ __forceinline__ void mma_tf32(float* d, const uint32_t* a, const uint32_t* b) {
    asm volatile(
        "mma.sync.aligned.m16n8k8.row.col.f32.tf32.tf32.f32 "
        "{%0,%1,%2,%3}, {%4,%5,%6,%7}, {%8,%9}, {%0,%1,%2,%3};"
        : "+f"(d[0]), "+f"(d[1]), "+f"(d[2]), "+f"(d[3])
        : "r"(a[0]), "r"(a[1]), "r"(a[2]), "r"(a[3]), "r"(b[0]), "r"(b[1]));
}

// ---------------------------------------------------------------------------
// GEMM: C[M,1024] = A[M,1024] * B[1024,1024]^T (+bias), tf32 tensor cores.
// CTA tile 128x128, BK=32, 256 threads (8 warps = 4M x 2N), warp tile 32x64.
// Smem: row-major [128][36] padded (conflict-free frag loads), double-buffered.
// ---------------------------------------------------------------------------
#define KP 36                          // padded row stride in floats
#define TILE_FLOATS (128 * KP)         // one A or B tile
#define BUF_FLOATS  (2 * TILE_FLOATS)  // A + B per stage
#define GEMM_SMEM   (2 * BUF_FLOATS * 4)   // 73728 bytes

__global__ __launch_bounds__(256) void gemm_tf32(
    const float* __restrict__ A, const float* __restrict__ B,
    const float* __restrict__ bias, float* __restrict__ C)
{
    extern __shared__ float smem[];
    const int tid  = threadIdx.x;
    const int lane = tid & 31, warp = tid >> 5;
    const int g    = lane >> 2, tig = lane & 3;
    const int wm   = warp >> 1, wn = warp & 1;
    const int bm   = blockIdx.y * 128;
    const int bn   = blockIdx.x * 128;

    // Load map: 4 float4 per thread per tile (A and B each).
    int lrow[4], lc4[4];
#pragma unroll
    for (int it = 0; it < 4; it++) {
        int v = tid + it * 256;
        lrow[it] = v >> 3;
        lc4[it]  = (v & 7) * 4;
    }

    float acc[2][8][4];
#pragma unroll
    for (int mi = 0; mi < 2; mi++)
#pragma unroll
        for (int ni = 0; ni < 8; ni++)
#pragma unroll
            for (int j = 0; j < 4; j++) acc[mi][ni][j] = 0.f;

    // Prologue: tile 0 -> stage 0
#pragma unroll
    for (int it = 0; it < 4; it++) {
        float4 a = *(const float4*)&A[(size_t)(bm + lrow[it]) * EMB + lc4[it]];
        float4 b = *(const float4*)&B[(size_t)(bn + lrow[it]) * EMB + lc4[it]];
        uint4 ua = make_uint4(f2tf32(a.x), f2tf32(a.y), f2tf32(a.z), f2tf32(a.w));
        uint4 ub = make_uint4(f2tf32(b.x), f2tf32(b.y), f2tf32(b.z), f2tf32(b.w));
        *(uint4*)&smem[lrow[it] * KP + lc4[it]] = ua;
        *(uint4*)&smem[TILE_FLOATS + lrow[it] * KP + lc4[it]] = ub;
    }
    __syncthreads();

    for (int ks = 0; ks < 32; ks++) {
        const int cur = ks & 1;
        const uint32_t* as = (const uint32_t*)(smem + cur * BUF_FLOATS) + (wm * 32) * KP;
        const uint32_t* bs = (const uint32_t*)(smem + cur * BUF_FLOATS + TILE_FLOATS) + (wn * 64) * KP;

        // Prefetch next tile into registers.
        float4 ra[4], rb[4];
        if (ks + 1 < 32) {
#pragma unroll
            for (int it = 0; it < 4; it++) {
                ra[it] = *(const float4*)&A[(size_t)(bm + lrow[it]) * EMB + (ks + 1) * 32 + lc4[it]];
                rb[it] = *(const float4*)&B[(size_t)(bn + lrow[it]) * EMB + (ks + 1) * 32 + lc4[it]];
            }
        }

        // Compute current tile: 4 k-steps of k8.
#pragma unroll
        for (int k0 = 0; k0 < 32; k0 += 8) {
            uint32_t af[2][4];
#pragma unroll
            for (int mi = 0; mi < 2; mi++) {
                int r = mi * 16 + g;
                af[mi][0] = as[(r    ) * KP + k0 + tig];
                af[mi][1] = as[(r + 8) * KP + k0 + tig];
                af[mi][2] = as[(r    ) * KP + k0 + tig + 4];
                af[mi][3] = as[(r + 8) * KP + k0 + tig + 4];
            }
#pragma unroll
            for (int ni = 0; ni < 8; ni++) {
                uint32_t bf[2];
                int nr = ni * 8 + g;
                bf[0] = bs[nr * KP + k0 + tig];
                bf[1] = bs[nr * KP + k0 + tig + 4];
                mma_tf32(acc[0][ni], af[0], bf);
                mma_tf32(acc[1][ni], af[1], bf);
            }
        }

        // Store next tile to the other stage.
        if (ks + 1 < 32) {
            const int nxt = cur ^ 1;
            float* an = smem + nxt * BUF_FLOATS;
            float* bnp = an + TILE_FLOATS;
#pragma unroll
            for (int it = 0; it < 4; it++) {
                uint4 ua = make_uint4(f2tf32(ra[it].x), f2tf32(ra[it].y),
                                      f2tf32(ra[it].z), f2tf32(ra[it].w));
                uint4 ub = make_uint4(f2tf32(rb[it].x), f2tf32(rb[it].y),
                                      f2tf32(rb[it].z), f2tf32(rb[it].w));
                *(uint4*)&an[lrow[it] * KP + lc4[it]]  = ua;
                *(uint4*)&bnp[lrow[it] * KP + lc4[it]] = ub;
            }
            __syncthreads();
        }
    }

    // Epilogue: write accumulators (+bias).
#pragma unroll
    for (int mi = 0; mi < 2; mi++) {
        int r0 = bm + wm * 32 + mi * 16 + g;
#pragma unroll
        for (int ni = 0; ni < 8; ni++) {
            int col = bn + wn * 64 + ni * 8 + 2 * tig;
            float b0 = 0.f, b1 = 0.f;
            if (bias) { b0 = bias[col]; b1 = bias[col + 1]; }
            *(float2*)&C[(size_t)r0 * EMB + col] =
                make_float2(acc[mi][ni][0] + b0, acc[mi][ni][1] + b1);
            *(float2*)&C[(size_t)(r0 + 8) * EMB + col] =
                make_float2(acc[mi][ni][2] + b0, acc[mi][ni][3] + b1);
        }
    }
}

// ---------------------------------------------------------------------------
// Flash attention (causal), fp32 — unchanged (proven, 689us).
// ---------------------------------------------------------------------------
__global__ __launch_bounds__(256) void attn_kernel(
    const float* __restrict__ Q, const float* __restrict__ K,
    const float* __restrict__ V, float* __restrict__ O)
{
    __shared__ float Qs[64 * 64];
    __shared__ float KPs[64 * 64];
    __shared__ float Vs[64 * 64];

    const int tid   = threadIdx.x;
    const int tn    = tid & 15;
    const int tm    = tid >> 4;
    const int qtile = blockIdx.x;
    const int bh    = blockIdx.y;
    const int b     = bh >> 4;
    const int h     = bh & 15;
    const size_t base = (size_t)b * TS * EMB + (size_t)h * HD;

#pragma unroll
    for (int it = 0; it < 4; it++) {
        int v   = tid + it * 256;
        int row = v >> 4;
        int dq  = (v & 15) * 4;
        float4 t = *(const float4*)&Q[base + (size_t)(qtile * 64 + row) * EMB + dq];
        Qs[(dq + 0) * 64 + row] = t.x; Qs[(dq + 1) * 64 + row] = t.y;
        Qs[(dq + 2) * 64 + row] = t.z; Qs[(dq + 3) * 64 + row] = t.w;
    }

    float m[4], l[4], o[4][4];
#pragma unroll
    for (int qi = 0; qi < 4; qi++) {
        m[qi] = -1e30f; l[qi] = 0.f;
#pragma unroll
        for (int di = 0; di < 4; di++) o[qi][di] = 0.f;
    }

    for (int kt = 0; kt <= qtile; kt++) {
        __syncthreads();
#pragma unroll
        for (int it = 0; it < 4; it++) {
            int v   = tid + it * 256;
            int row = v >> 4;
            int dq  = (v & 15) * 4;
            size_t gidx = base + (size_t)(kt * 64 + row) * EMB + dq;
            float4 tk = *(const float4*)&K[gidx];
            KPs[(dq + 0) * 64 + row] = tk.x; KPs[(dq + 1) * 64 + row] = tk.y;
            KPs[(dq + 2) * 64 + row] = tk.z; KPs[(dq + 3) * 64 + row] = tk.w;
            float4 tv = *(const float4*)&V[gidx];
            *(float4*)&Vs[row * 64 + dq] = tv;
        }
        __syncthreads();

        float s[4][4];
#pragma unroll
        for (int qi = 0; qi < 4; qi++)
#pragma unroll
            for (int ki = 0; ki < 4; ki++) s[qi][ki] = 0.f;
#pragma unroll
        for (int d = 0; d < 64; d++) {
            float4 qf = *(const float4*)&Qs[d * 64 + tm * 4];
            float4 kf = *(const float4*)&KPs[d * 64 + tn * 4];
            float qa[4] = {qf.x, qf.y, qf.z, qf.w};
            float ka[4] = {kf.x, kf.y, kf.z, kf.w};
#pragma unroll
            for (int qi = 0; qi < 4; qi++)
#pragma unroll
                for (int ki = 0; ki < 4; ki++) s[qi][ki] += qa[qi] * ka[ki];
        }

        const float sc = 0.125f;
        if (kt == qtile) {
#pragma unroll
            for (int qi = 0; qi < 4; qi++) {
                int qg = qtile * 64 + tm * 4 + qi;
#pragma unroll
                for (int ki = 0; ki < 4; ki++) {
                    int kg = kt * 64 + tn * 4 + ki;
                    s[qi][ki] = (kg > qg) ? -1e30f : s[qi][ki] * sc;
                }
            }
        } else {
#pragma unroll
            for (int qi = 0; qi < 4; qi++)
#pragma unroll
                for (int ki = 0; ki < 4; ki++) s[qi][ki] *= sc;
        }

        __syncthreads();

#pragma unroll
        for (int qi = 0; qi < 4; qi++) {
            float mt = fmaxf(fmaxf(s[qi][0], s[qi][1]), fmaxf(s[qi][2], s[qi][3]));
#pragma unroll
            for (int off = 1; off < 16; off <<= 1)
                mt = fmaxf(mt, __shfl_xor_sync(0xffffffffu, mt, off));
            float mn = fmaxf(m[qi], mt);
            float al = __expf(m[qi] - mn);
            float p[4], ps = 0.f;
#pragma unroll
            for (int ki = 0; ki < 4; ki++) { p[ki] = __expf(s[qi][ki] - mn); ps += p[ki]; }
#pragma unroll
            for (int off = 1; off < 16; off <<= 1)
                ps += __shfl_xor_sync(0xffffffffu, ps, off);
            l[qi] = l[qi] * al + ps;
            m[qi] = mn;
#pragma unroll
            for (int di = 0; di < 4; di++) o[qi][di] *= al;
            *(float4*)&KPs[(tm * 4 + qi) * 64 + tn * 4] = make_float4(p[0], p[1], p[2], p[3]);
        }
        __syncthreads();

#pragma unroll
        for (int kk = 0; kk < 64; kk++) {
            float4 vf = *(const float4*)&Vs[kk * 64 + tn * 4];
            float va[4] = {vf.x, vf.y, vf.z, vf.w};
            float pq[4];
#pragma unroll
            for (int qi = 0; qi < 4; qi++) pq[qi] = KPs[(tm * 4 + qi) * 64 + kk];
#pragma unroll
            for (int qi = 0; qi < 4; qi++)
#pragma unroll
                for (int di = 0; di < 4; di++) o[qi][di] += pq[qi] * va[di];
        }
    }

#pragma unroll
    for (int qi = 0; qi < 4; qi++) {
        float inv = 1.f / l[qi];
        float4 r = make_float4(o[qi][0] * inv, o[qi][1] * inv,
                               o[qi][2] * inv, o[qi][3] * inv);
        *(float4*)&O[base + (size_t)(qtile * 64 + tm * 4 + qi) * EMB + tn * 4] = r;
    }
}

// ---------------------------------------------------------------------------
extern "C" void kernel_launch(void* const* d_in, const int* in_sizes, int n_in,
                              void* d_out, int out_size)
{
    const float* x  = (const float*)d_in[0];
    // d_in[1] = mask (exact causal tril) -- applied analytically
    const float* Wq = (const float*)d_in[2];
    const float* Wk = (const float*)d_in[3];
    const float* Wv = (const float*)d_in[4];
    const float* Wo = (const float*)d_in[5];
    const float* bo = (const float*)d_in[6];
    float* out = (float*)d_out;

    float *Qb, *Kb, *Vb, *Ab;
    cudaGetSymbolAddress((void**)&Qb, g_Q);
    cudaGetSymbolAddress((void**)&Kb, g_K);
    cudaGetSymbolAddress((void**)&Vb, g_V);
    cudaGetSymbolAddress((void**)&Ab, g_A);

    cudaFuncSetAttribute(gemm_tf32, cudaFuncAttributeMaxDynamicSharedMemorySize, GEMM_SMEM);

    dim3 ggrid(EMB / 128, ROWS / 128);  // (8, 32)
    gemm_tf32<<<ggrid, 256, GEMM_SMEM>>>(x, Wq, nullptr, Qb);
    gemm_tf32<<<ggrid, 256, GEMM_SMEM>>>(x, Wk, nullptr, Kb);
    gemm_tf32<<<ggrid, 256, GEMM_SMEM>>>(x, Wv, nullptr, Vb);

    dim3 agrid(TS / 64, 2 * NHEADS);    // (32, 64)
    attn_kernel<<<agrid, 256>>>(Qb, Kb, Vb, Ab);

    gemm_tf32<<<ggrid, 256, GEMM_SMEM>>>(Ab, Wo, bo, out);
}

// round 4
// speedup vs baseline: 3.5241x; 2.2130x over previous
#include <cuda_runtime.h>
#include <cuda_bf16.h>
#include <cuda_fp16.h>
#include <cstdint>

// Problem: MaskedSelfAttention  B=2, S=2048, E=1024, H=16, D=64, causal.
// R4: attention moved to fp16 mma.m16n8k16 + FMA-pipe exp2 softmax.
//     GEMMs stay tf32 mma (R3, proven). tcgen05 unavailable (sm_103 target).

#define TS   2048
#define EMB  1024
#define NHEADS 16
#define HD   64
#define ROWS (2*TS)

__device__ float g_Q[ROWS*EMB];
__device__ float g_K[ROWS*EMB];
__device__ float g_V[ROWS*EMB];
__device__ float g_A[ROWS*EMB];

__device__ __forceinline__ uint32_t f2tf32(float f) {
    uint32_t u;
    asm("cvt.rna.tf32.f32 %0, %1;" : "=r"(u) : "f"(f));
    return u;
}

__device__ __forceinline__ void mma_tf32(float* d, const uint32_t* a, const uint32_t* b) {
    asm volatile(
        "mma.sync.aligned.m16n8k8.row.col.f32.tf32.tf32.f32 "
        "{%0,%1,%2,%3}, {%4,%5,%6,%7}, {%8,%9}, {%0,%1,%2,%3};"
        : "+f"(d[0]), "+f"(d[1]), "+f"(d[2]), "+f"(d[3])
        : "r"(a[0]), "r"(a[1]), "r"(a[2]), "r"(a[3]), "r"(b[0]), "r"(b[1]));
}

__device__ __forceinline__ void mma_f16(float* d, const uint32_t* a, const uint32_t* b) {
    asm volatile(
        "mma.sync.aligned.m16n8k16.row.col.f32.f16.f16.f32 "
        "{%0,%1,%2,%3}, {%4,%5,%6,%7}, {%8,%9}, {%0,%1,%2,%3};"
        : "+f"(d[0]), "+f"(d[1]), "+f"(d[2]), "+f"(d[3])
        : "r"(a[0]), "r"(a[1]), "r"(a[2]), "r"(a[3]), "r"(b[0]), "r"(b[1]));
}

// exp2 on the FMA/ALU pipes (no MUFU). d must be <= ~0; clamped below.
__device__ __forceinline__ float exp2p(float d) {
    d = fmaxf(d, -120.f);
    float t = d + 12582912.f;            // round-to-int in mantissa
    float f = d - (t - 12582912.f);      // f in [-0.5, 0.5]
    uint32_t e = (__float_as_uint(t) + (127u - 0x4B400000u)) << 23;
    float p = 1.3333558146e-3f;
    p = fmaf(p, f, 9.6181291076e-3f);
    p = fmaf(p, f, 5.5504108665e-2f);
    p = fmaf(p, f, 2.4022650696e-1f);
    p = fmaf(p, f, 6.9314718056e-1f);
    p = fmaf(p, f, 1.0f);
    return p * __uint_as_float(e);
}

__device__ __forceinline__ float qmax(float v) {
    v = fmaxf(v, __shfl_xor_sync(0xffffffffu, v, 1));
    v = fmaxf(v, __shfl_xor_sync(0xffffffffu, v, 2));
    return v;
}
__device__ __forceinline__ float qsum(float v) {
    v += __shfl_xor_sync(0xffffffffu, v, 1);
    v += __shfl_xor_sync(0xffffffffu, v, 2);
    return v;
}

// ---------------------------------------------------------------------------
// GEMM: C[M,1024] = A[M,1024]*B[1024,1024]^T (+bias), tf32 tensor cores (R3).
// ---------------------------------------------------------------------------
#define KP 36
#define TILE_FLOATS (128 * KP)
#define BUF_FLOATS  (2 * TILE_FLOATS)
#define GEMM_SMEM   (2 * BUF_FLOATS * 4)

__global__ __launch_bounds__(256) void gemm_tf32(
    const float* __restrict__ A, const float* __restrict__ B,
    const float* __restrict__ bias, float* __restrict__ C)
{
    extern __shared__ float smem[];
    const int tid  = threadIdx.x;
    const int lane = tid & 31, warp = tid >> 5;
    const int g    = lane >> 2, tig = lane & 3;
    const int wm   = warp >> 1, wn = warp & 1;
    const int bm   = blockIdx.y * 128;
    const int bn   = blockIdx.x * 128;

    int lrow[4], lc4[4];
#pragma unroll
    for (int it = 0; it < 4; it++) {
        int v = tid + it * 256;
        lrow[it] = v >> 3;
        lc4[it]  = (v & 7) * 4;
    }

    float acc[2][8][4];
#pragma unroll
    for (int mi = 0; mi < 2; mi++)
#pragma unroll
        for (int ni = 0; ni < 8; ni++)
#pragma unroll
            for (int j = 0; j < 4; j++) acc[mi][ni][j] = 0.f;

#pragma unroll
    for (int it = 0; it < 4; it++) {
        float4 a = *(const float4*)&A[(size_t)(bm + lrow[it]) * EMB + lc4[it]];
        float4 b = *(const float4*)&B[(size_t)(bn + lrow[it]) * EMB + lc4[it]];
        uint4 ua = make_uint4(f2tf32(a.x), f2tf32(a.y), f2tf32(a.z), f2tf32(a.w));
        uint4 ub = make_uint4(f2tf32(b.x), f2tf32(b.y), f2tf32(b.z), f2tf32(b.w));
        *(uint4*)&smem[lrow[it] * KP + lc4[it]] = ua;
        *(uint4*)&smem[TILE_FLOATS + lrow[it] * KP + lc4[it]] = ub;
    }
    __syncthreads();

    for (int ks = 0; ks < 32; ks++) {
        const int cur = ks & 1;
        const uint32_t* as = (const uint32_t*)(smem + cur * BUF_FLOATS) + (wm * 32) * KP;
        const uint32_t* bs = (const uint32_t*)(smem + cur * BUF_FLOATS + TILE_FLOATS) + (wn * 64) * KP;

        float4 ra[4], rb[4];
        if (ks + 1 < 32) {
#pragma unroll
            for (int it = 0; it < 4; it++) {
                ra[it] = *(const float4*)&A[(size_t)(bm + lrow[it]) * EMB + (ks + 1) * 32 + lc4[it]];
                rb[it] = *(const float4*)&B[(size_t)(bn + lrow[it]) * EMB + (ks + 1) * 32 + lc4[it]];
            }
        }

#pragma unroll
        for (int k0 = 0; k0 < 32; k0 += 8) {
            uint32_t af[2][4];
#pragma unroll
            for (int mi = 0; mi < 2; mi++) {
                int r = mi * 16 + g;
                af[mi][0] = as[(r    ) * KP + k0 + tig];
                af[mi][1] = as[(r + 8) * KP + k0 + tig];
                af[mi][2] = as[(r    ) * KP + k0 + tig + 4];
                af[mi][3] = as[(r + 8) * KP + k0 + tig + 4];
            }
#pragma unroll
            for (int ni = 0; ni < 8; ni++) {
                uint32_t bf[2];
                int nr = ni * 8 + g;
                bf[0] = bs[nr * KP + k0 + tig];
                bf[1] = bs[nr * KP + k0 + tig + 4];
                mma_tf32(acc[0][ni], af[0], bf);
                mma_tf32(acc[1][ni], af[1], bf);
            }
        }

        if (ks + 1 < 32) {
            const int nxt = cur ^ 1;
            float* an  = smem + nxt * BUF_FLOATS;
            float* bnp = an + TILE_FLOATS;
#pragma unroll
            for (int it = 0; it < 4; it++) {
                uint4 ua = make_uint4(f2tf32(ra[it].x), f2tf32(ra[it].y),
                                      f2tf32(ra[it].z), f2tf32(ra[it].w));
                uint4 ub = make_uint4(f2tf32(rb[it].x), f2tf32(rb[it].y),
                                      f2tf32(rb[it].z), f2tf32(rb[it].w));
                *(uint4*)&an[lrow[it] * KP + lc4[it]]  = ua;
                *(uint4*)&bnp[lrow[it] * KP + lc4[it]] = ub;
            }
            __syncthreads();
        }
    }

#pragma unroll
    for (int mi = 0; mi < 2; mi++) {
        int r0 = bm + wm * 32 + mi * 16 + g;
#pragma unroll
        for (int ni = 0; ni < 8; ni++) {
            int col = bn + wn * 64 + ni * 8 + 2 * tig;
            float b0 = 0.f, b1 = 0.f;
            if (bias) { b0 = bias[col]; b1 = bias[col + 1]; }
            *(float2*)&C[(size_t)r0 * EMB + col] =
                make_float2(acc[mi][ni][0] + b0, acc[mi][ni][1] + b1);
            *(float2*)&C[(size_t)(r0 + 8) * EMB + col] =
                make_float2(acc[mi][ni][2] + b0, acc[mi][ni][3] + b1);
        }
    }
}

// ---------------------------------------------------------------------------
// Flash attention (causal) with fp16 tensor cores + polynomial exp2 softmax.
// CTA: 128 queries of one (b,h); 8 warps (16 q-rows each); 64-key tiles.
// Smem (half): Ks[64 key][72 d], Vt[64 d][72 key], Ps[128 q][72 key]
//   (Ps doubles as Q staging). Strides of 72 halves = 36 words: conflict-free
//   fragment access (36*g+tig ≡ 4g+tig mod 32).
// ---------------------------------------------------------------------------
#define ASTR 72
#define AW   36   // stride in 32-bit words

__global__ __launch_bounds__(256, 2) void attn_mma(
    const float* __restrict__ Q, const float* __restrict__ K,
    const float* __restrict__ V, float* __restrict__ O)
{
    __shared__ __half Ks[64 * ASTR];
    __shared__ __half Vt[64 * ASTR];
    __shared__ __half Ps[128 * ASTR];

    const int tid  = threadIdx.x;
    const int lane = tid & 31, w = tid >> 5;
    const int g    = lane >> 2, tig = lane & 3;
    const int qt   = 15 - blockIdx.x;          // heavy CTAs first
    const int bh   = blockIdx.y;
    const int b    = bh >> 4, h = bh & 15;
    const size_t base  = (size_t)b * TS * EMB + (size_t)h * HD;
    const int    qbase = qt * 128;

    uint32_t* KsW = (uint32_t*)Ks;
    uint32_t* VtW = (uint32_t*)Vt;
    uint32_t* PsW = (uint32_t*)Ps;

    // ---- Stage Q tile into Ps (as half), then lift to register fragments.
#pragma unroll
    for (int it = 0; it < 8; it++) {
        int v = tid + it * 256;
        int row = v >> 4, c4 = (v & 15) * 4;
        float4 t = *(const float4*)&Q[base + (size_t)(qbase + row) * EMB + c4];
        ((__half2*)Ps)[row * AW + c4 / 2]     = __floats2half2_rn(t.x, t.y);
        ((__half2*)Ps)[row * AW + c4 / 2 + 1] = __floats2half2_rn(t.z, t.w);
    }
    __syncthreads();

    uint32_t qa[4][4];
    {
        const int r0 = w * 16 + g;
#pragma unroll
        for (int kc = 0; kc < 4; kc++) {
            qa[kc][0] = PsW[(r0    ) * AW + kc * 8 + tig];
            qa[kc][1] = PsW[(r0 + 8) * AW + kc * 8 + tig];
            qa[kc][2] = PsW[(r0    ) * AW + kc * 8 + 4 + tig];
            qa[kc][3] = PsW[(r0 + 8) * AW + kc * 8 + 4 + tig];
        }
    }
    __syncthreads();   // Ps free for P use

    float m0 = -1e30f, m1 = -1e30f, l0 = 0.f, l1 = 0.f;
    float o[8][4];
#pragma unroll
    for (int ni = 0; ni < 8; ni++)
#pragma unroll
        for (int j = 0; j < 4; j++) o[ni][j] = 0.f;

    const float scale2 = 0.125f * 1.44269504089f;   // 1/sqrt(64) * log2(e)
    const int nkt = 2 * qt + 2;
    const int qrow_max = qbase + w * 16 + 15;

    for (int kt = 0; kt < nkt; kt++) {
        __syncthreads();   // prior compute done; safe to overwrite Ks/Vt
        // K tile: [key][d] as half
#pragma unroll
        for (int it = 0; it < 4; it++) {
            int v = tid + it * 256;
            int row = v >> 4, c4 = (v & 15) * 4;
            float4 t = *(const float4*)&K[base + (size_t)(kt * 64 + row) * EMB + c4];
            ((__half2*)Ks)[row * AW + c4 / 2]     = __floats2half2_rn(t.x, t.y);
            ((__half2*)Ks)[row * AW + c4 / 2 + 1] = __floats2half2_rn(t.z, t.w);
        }
        // V tile transposed: Vt[d][key], key pairs packed per half2
#pragma unroll
        for (int it = 0; it < 2; it++) {
            int u  = tid + it * 256;
            int kp = u & 31, c4 = (u >> 5) * 4;
            const float* va = &V[base + (size_t)(kt * 64 + 2 * kp) * EMB + c4];
            const float* vb = va + EMB;
            float4 fa = *(const float4*)va;
            float4 fb = *(const float4*)vb;
            ((__half2*)Vt)[(c4 + 0) * AW + kp] = __floats2half2_rn(fa.x, fb.x);
            ((__half2*)Vt)[(c4 + 1) * AW + kp] = __floats2half2_rn(fa.y, fb.y);
            ((__half2*)Vt)[(c4 + 2) * AW + kp] = __floats2half2_rn(fa.z, fb.z);
            ((__half2*)Vt)[(c4 + 3) * AW + kp] = __floats2half2_rn(fa.w, fb.w);
        }
        __syncthreads();

        if (kt * 64 > qrow_max) continue;   // warp fully masked for this tile

        // ---- Scores: sc[8][4] = Q . K^T fragments
        float sc[8][4];
#pragma unroll
        for (int ni = 0; ni < 8; ni++) {
            sc[ni][0] = sc[ni][1] = sc[ni][2] = sc[ni][3] = 0.f;
            int nr = ni * 8 + g;
#pragma unroll
            for (int kc = 0; kc < 4; kc++) {
                uint32_t bf[2];
                bf[0] = KsW[nr * AW + kc * 8 + tig];
                bf[1] = KsW[nr * AW + kc * 8 + 4 + tig];
                mma_f16(sc[ni], qa[kc], bf);
            }
        }

        // ---- Scale + causal mask (scores *= 1/8*log2e; masked -> -inf)
        const bool diag = (kt * 64 + 63 > qbase + w * 16);
        const int qg0 = qbase + w * 16 + g, qg1 = qg0 + 8;
#pragma unroll
        for (int ni = 0; ni < 8; ni++) {
#pragma unroll
            for (int j = 0; j < 4; j++) sc[ni][j] *= scale2;
            if (diag) {
                int kg = kt * 64 + ni * 8 + 2 * tig;
                if (kg     > qg0) sc[ni][0] = -1e30f;
                if (kg + 1 > qg0) sc[ni][1] = -1e30f;
                if (kg     > qg1) sc[ni][2] = -1e30f;
                if (kg + 1 > qg1) sc[ni][3] = -1e30f;
            }
        }

        // ---- Online softmax (base-2 domain), P -> Ps (per-warp region)
        float rm0 = -1e30f, rm1 = -1e30f;
#pragma unroll
        for (int ni = 0; ni < 8; ni++) {
            rm0 = fmaxf(rm0, fmaxf(sc[ni][0], sc[ni][1]));
            rm1 = fmaxf(rm1, fmaxf(sc[ni][2], sc[ni][3]));
        }
        rm0 = qmax(rm0); rm1 = qmax(rm1);
        float mn0 = fmaxf(m0, rm0), mn1 = fmaxf(m1, rm1);
        float a0 = exp2p(m0 - mn0), a1 = exp2p(m1 - mn1);
        m0 = mn0; m1 = mn1;
#pragma unroll
        for (int ni = 0; ni < 8; ni++) {
            o[ni][0] *= a0; o[ni][1] *= a0;
            o[ni][2] *= a1; o[ni][3] *= a1;
        }
        float s0 = 0.f, s1 = 0.f;
        const int pr0 = w * 16 + g;
#pragma unroll
        for (int ni = 0; ni < 8; ni++) {
            float p0 = exp2p(sc[ni][0] - mn0);
            float p1 = exp2p(sc[ni][1] - mn0);
            float p2 = exp2p(sc[ni][2] - mn1);
            float p3 = exp2p(sc[ni][3] - mn1);
            s0 += p0 + p1; s1 += p2 + p3;
            ((__half2*)Ps)[(pr0    ) * AW + ni * 4 + tig] = __floats2half2_rn(p0, p1);
            ((__half2*)Ps)[(pr0 + 8) * AW + ni * 4 + tig] = __floats2half2_rn(p2, p3);
        }
        l0 = l0 * a0 + qsum(s0);
        l1 = l1 * a1 + qsum(s1);
        __syncwarp();

        // ---- PV: o += P . V
#pragma unroll
        for (int kc = 0; kc < 4; kc++) {
            uint32_t pa[4];
            pa[0] = PsW[(pr0    ) * AW + kc * 8 + tig];
            pa[1] = PsW[(pr0 + 8) * AW + kc * 8 + tig];
            pa[2] = PsW[(pr0    ) * AW + kc * 8 + 4 + tig];
            pa[3] = PsW[(pr0 + 8) * AW + kc * 8 + 4 + tig];
#pragma unroll
            for (int nd = 0; nd < 8; nd++) {
                uint32_t bf[2];
                int dr = nd * 8 + g;
                bf[0] = VtW[dr * AW + kc * 8 + tig];
                bf[1] = VtW[dr * AW + kc * 8 + 4 + tig];
                mma_f16(o[nd], pa, bf);
            }
        }
        __syncwarp();   // PV reads of Ps done before next tile's stores
    }

    // ---- Normalize + store
    const float inv0 = 1.f / l0, inv1 = 1.f / l1;
    const int q0 = qbase + w * 16 + g;
#pragma unroll
    for (int nd = 0; nd < 8; nd++) {
        int col = nd * 8 + 2 * tig;
        *(float2*)&O[base + (size_t)q0 * EMB + col] =
            make_float2(o[nd][0] * inv0, o[nd][1] * inv0);
        *(float2*)&O[base + (size_t)(q0 + 8) * EMB + col] =
            make_float2(o[nd][2] * inv1, o[nd][3] * inv1);
    }
}

// ---------------------------------------------------------------------------
extern "C" void kernel_launch(void* const* d_in, const int* in_sizes, int n_in,
                              void* d_out, int out_size)
{
    const float* x  = (const float*)d_in[0];
    // d_in[1] = mask (exact causal tril) -- applied analytically
    const float* Wq = (const float*)d_in[2];
    const float* Wk = (const float*)d_in[3];
    const float* Wv = (const float*)d_in[4];
    const float* Wo = (const float*)d_in[5];
    const float* bo = (const float*)d_in[6];
    float* out = (float*)d_out;

    float *Qb, *Kb, *Vb, *Ab;
    cudaGetSymbolAddress((void**)&Qb, g_Q);
    cudaGetSymbolAddress((void**)&Kb, g_K);
    cudaGetSymbolAddress((void**)&Vb, g_V);
    cudaGetSymbolAddress((void**)&Ab, g_A);

    cudaFuncSetAttribute(gemm_tf32, cudaFuncAttributeMaxDynamicSharedMemorySize, GEMM_SMEM);

    dim3 ggrid(EMB / 128, ROWS / 128);  // (8, 32)
    gemm_tf32<<<ggrid, 256, GEMM_SMEM>>>(x, Wq, nullptr, Qb);
    gemm_tf32<<<ggrid, 256, GEMM_SMEM>>>(x, Wk, nullptr, Kb);
    gemm_tf32<<<ggrid, 256, GEMM_SMEM>>>(x, Wv, nullptr, Vb);

    dim3 agrid(16, 2 * NHEADS);         // (16, 32): 128-query tiles x (b,h)
    attn_mma<<<agrid, 256>>>(Qb, Kb, Vb, Ab);

    gemm_tf32<<<ggrid, 256, GEMM_SMEM>>>(Ab, Wo, bo, out);
}

// round 6
// speedup vs baseline: 4.5902x; 1.3025x over previous
#include <cuda_runtime.h>
#include <cuda_bf16.h>
#include <cuda_fp16.h>
#include <cstdint>

// Problem: MaskedSelfAttention  B=2, S=2048, E=1024, H=16, D=64, causal.
// R6 (= R5 fixed): GEMMs -> fp16 mma.m16n8k16, QKV fused into one launch.
//     Attention unchanged from R4 (fp16 mma + poly exp2).

#define TS   2048
#define EMB  1024
#define NHEADS 16
#define HD   64
#define ROWS (2*TS)

__device__ float g_Q[ROWS*EMB];
__device__ float g_K[ROWS*EMB];
__device__ float g_V[ROWS*EMB];
__device__ float g_A[ROWS*EMB];

__device__ __forceinline__ void mma_f16(float* d, const uint32_t* a, const uint32_t* b) {
    asm volatile(
        "mma.sync.aligned.m16n8k16.row.col.f32.f16.f16.f32 "
        "{%0,%1,%2,%3}, {%4,%5,%6,%7}, {%8,%9}, {%0,%1,%2,%3};"
        : "+f"(d[0]), "+f"(d[1]), "+f"(d[2]), "+f"(d[3])
        : "r"(a[0]), "r"(a[1]), "r"(a[2]), "r"(a[3]), "r"(b[0]), "r"(b[1]));
}

__device__ __forceinline__ uint32_t pack_h2(float x, float y) {
    __half2 h = __floats2half2_rn(x, y);
    return *(uint32_t*)&h;
}

// exp2 on the FMA/ALU pipes (no MUFU).
__device__ __forceinline__ float exp2p(float d) {
    d = fmaxf(d, -120.f);
    float t = d + 12582912.f;
    float f = d - (t - 12582912.f);
    uint32_t e = (__float_as_uint(t) + (127u - 0x4B400000u)) << 23;
    float p = 1.3333558146e-3f;
    p = fmaf(p, f, 9.6181291076e-3f);
    p = fmaf(p, f, 5.5504108665e-2f);
    p = fmaf(p, f, 2.4022650696e-1f);
    p = fmaf(p, f, 6.9314718056e-1f);
    p = fmaf(p, f, 1.0f);
    return p * __uint_as_float(e);
}

__device__ __forceinline__ float qmax(float v) {
    v = fmaxf(v, __shfl_xor_sync(0xffffffffu, v, 1));
    v = fmaxf(v, __shfl_xor_sync(0xffffffffu, v, 2));
    return v;
}
__device__ __forceinline__ float qsum(float v) {
    v += __shfl_xor_sync(0xffffffffu, v, 1);
    v += __shfl_xor_sync(0xffffffffu, v, 2);
    return v;
}

// ---------------------------------------------------------------------------
// fp16 GEMM core: C[128x128 tile] = A[M,1024] * B[1024,1024]^T (+bias).
// CTA 128x128, BK=32 halves->16 words, 256 threads (8 warps = 4M x 2N),
// double-buffered. Smem word stride KW=20: frag address 20g+tig mod 32 hits
// all 32 banks distinct -> conflict-free LDS; uint2 stores also clean.
// ---------------------------------------------------------------------------
#define KW 20                            // word stride per row
#define TILE_W (128 * KW)                // words per tile
#define BUF_W  (2 * TILE_W)              // A + B per stage

__device__ __forceinline__ void gemm_f16_body(
    const float* __restrict__ A, const float* __restrict__ B,
    const float* __restrict__ bias, float* __restrict__ C,
    int bm, int bn, uint32_t* sm)
{
    const int tid  = threadIdx.x;
    const int lane = tid & 31, warp = tid >> 5;
    const int g    = lane >> 2, tig = lane & 3;
    const int wm   = warp >> 1, wn = warp & 1;

    int lrow[4], lc4[4];
#pragma unroll
    for (int it = 0; it < 4; it++) {
        int v = tid + it * 256;
        lrow[it] = v >> 3;
        lc4[it]  = (v & 7) * 4;          // float col within BK=32
    }

    float acc[2][8][4];
#pragma unroll
    for (int mi = 0; mi < 2; mi++)
#pragma unroll
        for (int ni = 0; ni < 8; ni++)
#pragma unroll
            for (int j = 0; j < 4; j++) acc[mi][ni][j] = 0.f;

    // Prologue: tile 0 -> stage 0
#pragma unroll
    for (int it = 0; it < 4; it++) {
        float4 a = *(const float4*)&A[(size_t)(bm + lrow[it]) * EMB + lc4[it]];
        float4 b = *(const float4*)&B[(size_t)(bn + lrow[it]) * EMB + lc4[it]];
        *(uint2*)&sm[lrow[it] * KW + lc4[it] / 2] =
            make_uint2(pack_h2(a.x, a.y), pack_h2(a.z, a.w));
        *(uint2*)&sm[TILE_W + lrow[it] * KW + lc4[it] / 2] =
            make_uint2(pack_h2(b.x, b.y), pack_h2(b.z, b.w));
    }
    __syncthreads();

    for (int ks = 0; ks < 32; ks++) {
        const int cur = ks & 1;
        const uint32_t* as = sm + cur * BUF_W + (wm * 32) * KW;
        const uint32_t* bs = sm + cur * BUF_W + TILE_W + (wn * 64) * KW;

        float4 ra[4], rb[4];
        if (ks + 1 < 32) {
#pragma unroll
            for (int it = 0; it < 4; it++) {
                ra[it] = *(const float4*)&A[(size_t)(bm + lrow[it]) * EMB + (ks + 1) * 32 + lc4[it]];
                rb[it] = *(const float4*)&B[(size_t)(bn + lrow[it]) * EMB + (ks + 1) * 32 + lc4[it]];
            }
        }

        // 2 k16 steps per BK=32 (word offsets 0, 8)
#pragma unroll
        for (int kk = 0; kk < 2; kk++) {
            const int k0 = kk * 8;
            uint32_t af[2][4];
#pragma unroll
            for (int mi = 0; mi < 2; mi++) {
                int r = mi * 16 + g;
                af[mi][0] = as[(r    ) * KW + k0 + tig];
                af[mi][1] = as[(r + 8) * KW + k0 + tig];
                af[mi][2] = as[(r    ) * KW + k0 + 4 + tig];
                af[mi][3] = as[(r + 8) * KW + k0 + 4 + tig];
            }
#pragma unroll
            for (int ni = 0; ni < 8; ni++) {
                uint32_t bf[2];
                int nr = ni * 8 + g;
                bf[0] = bs[nr * KW + k0 + tig];
                bf[1] = bs[nr * KW + k0 + 4 + tig];
                mma_f16(acc[0][ni], af[0], bf);
                mma_f16(acc[1][ni], af[1], bf);
            }
        }

        if (ks + 1 < 32) {
            const int nxt = cur ^ 1;
            uint32_t* an  = sm + nxt * BUF_W;
            uint32_t* bnp = an + TILE_W;
#pragma unroll
            for (int it = 0; it < 4; it++) {
                *(uint2*)&an[lrow[it] * KW + lc4[it] / 2] =
                    make_uint2(pack_h2(ra[it].x, ra[it].y), pack_h2(ra[it].z, ra[it].w));
                *(uint2*)&bnp[lrow[it] * KW + lc4[it] / 2] =
                    make_uint2(pack_h2(rb[it].x, rb[it].y), pack_h2(rb[it].z, rb[it].w));
            }
            __syncthreads();
        }
    }

#pragma unroll
    for (int mi = 0; mi < 2; mi++) {
        int r0 = bm + wm * 32 + mi * 16 + g;
#pragma unroll
        for (int ni = 0; ni < 8; ni++) {
            int col = bn + wn * 64 + ni * 8 + 2 * tig;
            float b0 = 0.f, b1 = 0.f;
            if (bias) { b0 = bias[col]; b1 = bias[col + 1]; }
            *(float2*)&C[(size_t)r0 * EMB + col] =
                make_float2(acc[mi][ni][0] + b0, acc[mi][ni][1] + b1);
            *(float2*)&C[(size_t)(r0 + 8) * EMB + col] =
                make_float2(acc[mi][ni][2] + b0, acc[mi][ni][3] + b1);
        }
    }
}

// Fused QKV: grid (24, 32); blockIdx.x>>3 selects {Wq,Wk,Wv} -> {Q,K,V}.
__global__ __launch_bounds__(256) void gemm_qkv(
    const float* __restrict__ X,
    const float* __restrict__ Wq, const float* __restrict__ Wk,
    const float* __restrict__ Wv,
    float* __restrict__ Qo, float* __restrict__ Ko, float* __restrict__ Vo)
{
    __shared__ uint32_t sm[2 * BUF_W];
    const int wb = blockIdx.x >> 3;
    const int bn = (blockIdx.x & 7) * 128;
    const int bm = blockIdx.y * 128;
    const float* B = (wb == 0) ? Wq : (wb == 1) ? Wk : Wv;
    float*       C = (wb == 0) ? Qo : (wb == 1) ? Ko : Vo;
    gemm_f16_body(X, B, nullptr, C, bm, bn, sm);
}

__global__ __launch_bounds__(256) void gemm_out(
    const float* __restrict__ A, const float* __restrict__ W,
    const float* __restrict__ bias, float* __restrict__ C)
{
    __shared__ uint32_t sm[2 * BUF_W];
    gemm_f16_body(A, W, bias, C, blockIdx.y * 128, blockIdx.x * 128, sm);
}

// ---------------------------------------------------------------------------
// Flash attention (causal), fp16 mma + polynomial exp2 softmax (R4, proven).
// ---------------------------------------------------------------------------
#define ASTR 72
#define AW   36

__global__ __launch_bounds__(256, 2) void attn_mma(
    const float* __restrict__ Q, const float* __restrict__ K,
    const float* __restrict__ V, float* __restrict__ O)
{
    __shared__ __half Ks[64 * ASTR];
    __shared__ __half Vt[64 * ASTR];
    __shared__ __half Ps[128 * ASTR];

    const int tid  = threadIdx.x;
    const int lane = tid & 31, w = tid >> 5;
    const int g    = lane >> 2, tig = lane & 3;
    const int qt   = 15 - blockIdx.x;
    const int bh   = blockIdx.y;
    const int b    = bh >> 4, h = bh & 15;
    const size_t base  = (size_t)b * TS * EMB + (size_t)h * HD;
    const int    qbase = qt * 128;

    uint32_t* KsW = (uint32_t*)Ks;
    uint32_t* VtW = (uint32_t*)Vt;
    uint32_t* PsW = (uint32_t*)Ps;

#pragma unroll
    for (int it = 0; it < 8; it++) {
        int v = tid + it * 256;
        int row = v >> 4, c4 = (v & 15) * 4;
        float4 t = *(const float4*)&Q[base + (size_t)(qbase + row) * EMB + c4];
        ((__half2*)Ps)[row * AW + c4 / 2]     = __floats2half2_rn(t.x, t.y);
        ((__half2*)Ps)[row * AW + c4 / 2 + 1] = __floats2half2_rn(t.z, t.w);
    }
    __syncthreads();

    uint32_t qa[4][4];
    {
        const int r0 = w * 16 + g;
#pragma unroll
        for (int kc = 0; kc < 4; kc++) {
            qa[kc][0] = PsW[(r0    ) * AW + kc * 8 + tig];
            qa[kc][1] = PsW[(r0 + 8) * AW + kc * 8 + tig];
            qa[kc][2] = PsW[(r0    ) * AW + kc * 8 + 4 + tig];
            qa[kc][3] = PsW[(r0 + 8) * AW + kc * 8 + 4 + tig];
        }
    }
    __syncthreads();

    float m0 = -1e30f, m1 = -1e30f, l0 = 0.f, l1 = 0.f;
    float o[8][4];
#pragma unroll
    for (int ni = 0; ni < 8; ni++)
#pragma unroll
        for (int j = 0; j < 4; j++) o[ni][j] = 0.f;

    const float scale2 = 0.125f * 1.44269504089f;
    const int nkt = 2 * qt + 2;
    const int qrow_max = qbase + w * 16 + 15;

    for (int kt = 0; kt < nkt; kt++) {
        __syncthreads();
#pragma unroll
        for (int it = 0; it < 4; it++) {
            int v = tid + it * 256;
            int row = v >> 4, c4 = (v & 15) * 4;
            float4 t = *(const float4*)&K[base + (size_t)(kt * 64 + row) * EMB + c4];
            ((__half2*)Ks)[row * AW + c4 / 2]     = __floats2half2_rn(t.x, t.y);
            ((__half2*)Ks)[row * AW + c4 / 2 + 1] = __floats2half2_rn(t.z, t.w);
        }
#pragma unroll
        for (int it = 0; it < 2; it++) {
            int u  = tid + it * 256;
            int kp = u & 31, c4 = (u >> 5) * 4;
            const float* va = &V[base + (size_t)(kt * 64 + 2 * kp) * EMB + c4];
            const float* vb = va + EMB;
            float4 fa = *(const float4*)va;
            float4 fb = *(const float4*)vb;
            ((__half2*)Vt)[(c4 + 0) * AW + kp] = __floats2half2_rn(fa.x, fb.x);
            ((__half2*)Vt)[(c4 + 1) * AW + kp] = __floats2half2_rn(fa.y, fb.y);
            ((__half2*)Vt)[(c4 + 2) * AW + kp] = __floats2half2_rn(fa.z, fb.z);
            ((__half2*)Vt)[(c4 + 3) * AW + kp] = __floats2half2_rn(fa.w, fb.w);
        }
        __syncthreads();

        if (kt * 64 > qrow_max) continue;

        float sc[8][4];
#pragma unroll
        for (int ni = 0; ni < 8; ni++) {
            sc[ni][0] = sc[ni][1] = sc[ni][2] = sc[ni][3] = 0.f;
            int nr = ni * 8 + g;
#pragma unroll
            for (int kc = 0; kc < 4; kc++) {
                uint32_t bf[2];
                bf[0] = KsW[nr * AW + kc * 8 + tig];
                bf[1] = KsW[nr * AW + kc * 8 + 4 + tig];
                mma_f16(sc[ni], qa[kc], bf);
            }
        }

        const bool diag = (kt * 64 + 63 > qbase + w * 16);
        const int qg0 = qbase + w * 16 + g, qg1 = qg0 + 8;
#pragma unroll
        for (int ni = 0; ni < 8; ni++) {
#pragma unroll
            for (int j = 0; j < 4; j++) sc[ni][j] *= scale2;
            if (diag) {
                int kg = kt * 64 + ni * 8 + 2 * tig;
                if (kg     > qg0) sc[ni][0] = -1e30f;
                if (kg + 1 > qg0) sc[ni][1] = -1e30f;
                if (kg     > qg1) sc[ni][2] = -1e30f;
                if (kg + 1 > qg1) sc[ni][3] = -1e30f;
            }
        }

        float rm0 = -1e30f, rm1 = -1e30f;
#pragma unroll
        for (int ni = 0; ni < 8; ni++) {
            rm0 = fmaxf(rm0, fmaxf(sc[ni][0], sc[ni][1]));
            rm1 = fmaxf(rm1, fmaxf(sc[ni][2], sc[ni][3]));
        }
        rm0 = qmax(rm0); rm1 = qmax(rm1);
        float mn0 = fmaxf(m0, rm0), mn1 = fmaxf(m1, rm1);
        float a0 = exp2p(m0 - mn0), a1 = exp2p(m1 - mn1);
        m0 = mn0; m1 = mn1;
#pragma unroll
        for (int ni = 0; ni < 8; ni++) {
            o[ni][0] *= a0; o[ni][1] *= a0;
            o[ni][2] *= a1; o[ni][3] *= a1;
        }
        float s0 = 0.f, s1 = 0.f;
        const int pr0 = w * 16 + g;
#pragma unroll
        for (int ni = 0; ni < 8; ni++) {
            float p0 = exp2p(sc[ni][0] - mn0);
            float p1 = exp2p(sc[ni][1] - mn0);
            float p2 = exp2p(sc[ni][2] - mn1);
            float p3 = exp2p(sc[ni][3] - mn1);
            s0 += p0 + p1; s1 += p2 + p3;
            ((__half2*)Ps)[(pr0    ) * AW + ni * 4 + tig] = __floats2half2_rn(p0, p1);
            ((__half2*)Ps)[(pr0 + 8) * AW + ni * 4 + tig] = __floats2half2_rn(p2, p3);
        }
        l0 = l0 * a0 + qsum(s0);
        l1 = l1 * a1 + qsum(s1);
        __syncwarp();

#pragma unroll
        for (int kc = 0; kc < 4; kc++) {
            uint32_t pa[4];
            pa[0] = PsW[(pr0    ) * AW + kc * 8 + tig];
            pa[1] = PsW[(pr0 + 8) * AW + kc * 8 + tig];
            pa[2] = PsW[(pr0    ) * AW + kc * 8 + 4 + tig];
            pa[3] = PsW[(pr0 + 8) * AW + kc * 8 + 4 + tig];
#pragma unroll
            for (int nd = 0; nd < 8; nd++) {
                uint32_t bf[2];
                int dr = nd * 8 + g;
                bf[0] = VtW[dr * AW + kc * 8 + tig];
                bf[1] = VtW[dr * AW + kc * 8 + 4 + tig];
                mma_f16(o[nd], pa, bf);
            }
        }
        __syncwarp();
    }

    const float inv0 = 1.f / l0, inv1 = 1.f / l1;
    const int q0 = qbase + w * 16 + g;
#pragma unroll
    for (int nd = 0; nd < 8; nd++) {
        int col = nd * 8 + 2 * tig;
        *(float2*)&O[base + (size_t)q0 * EMB + col] =
            make_float2(o[nd][0] * inv0, o[nd][1] * inv0);
        *(float2*)&O[base + (size_t)(q0 + 8) * EMB + col] =
            make_float2(o[nd][2] * inv1, o[nd][3] * inv1);
    }
}

// ---------------------------------------------------------------------------
extern "C" void kernel_launch(void* const* d_in, const int* in_sizes, int n_in,
                              void* d_out, int out_size)
{
    const float* x  = (const float*)d_in[0];
    // d_in[1] = mask (exact causal tril) -- applied analytically
    const float* Wq = (const float*)d_in[2];
    const float* Wk = (const float*)d_in[3];
    const float* Wv = (const float*)d_in[4];
    const float* Wo = (const float*)d_in[5];
    const float* bo = (const float*)d_in[6];
    float* out = (float*)d_out;

    float *Qb, *Kb, *Vb, *Ab;
    cudaGetSymbolAddress((void**)&Qb, g_Q);
    cudaGetSymbolAddress((void**)&Kb, g_K);
    cudaGetSymbolAddress((void**)&Vb, g_V);
    cudaGetSymbolAddress((void**)&Ab, g_A);

    dim3 qkvgrid(24, ROWS / 128);       // (24, 32)
    gemm_qkv<<<qkvgrid, 256>>>(x, Wq, Wk, Wv, Qb, Kb, Vb);

    dim3 agrid(16, 2 * NHEADS);         // (16, 32)
    attn_mma<<<agrid, 256>>>(Qb, Kb, Vb, Ab);

    dim3 ogrid(EMB / 128, ROWS / 128);  // (8, 32)
    gemm_out<<<ogrid, 256>>>(Ab, Wo, bo, out);
}